// round 16
// baseline (speedup 1.0000x reference)
#include <cuda_runtime.h>
#include <cstdint>

#define Bc 2
#define Hc 16
#define Sc 2048
#define Dc 64
#define BHc (Bc*Hc)
#define MT 128
#define NT 128
#define NKV (Sc/NT)
#define THREADS 256

// interleaved uint4 strides (uint4 units)
#define KS4 20            // K row: 16 data + 4 pad  (20%8==4 -> conflict-free LDS.128)
#define VS4 66            // V row: 64 data + 2 pad  (66%8==2 -> conflict-free LDS.128)

#define KREGB (NT*KS4*16)           // 40960 B
#define VREGB ((NT/4)*VS4*16)       // 33792 B (32 g-rows)
#define PSTAGE (KREGB + VREGB)      // 74752 B per stage
#define OFF_MASKALL (2*PSTAGE)      // 149504
#define SMEM_BYTES (OFF_MASKALL + Sc*4)   // 157696
#define DSMEM (2*KREGB + Sc*4)            // 90112

__device__ float g_d[BHc*Sc];       // row denominators
// pre-split interleaved bf16 buffers (32 MB static scratch)
__device__ uint4 g_kq[(size_t)BHc*Sc*16];      // [row][q]: {hi(c0),hi(c0+4),lo(c0),lo(c0+4)}
__device__ uint4 g_v [(size_t)BHc*16*2048];    // [bh][tile][g][n]: {vhi(kp),vhi(kp+4),vlo(kp),vlo(kp+4)}

__device__ __forceinline__ uint32_t smem_u32(const void* p){
    uint32_t a;
    asm("{ .reg .u64 t; cvta.to.shared.u64 t, %1; cvt.u32.u64 %0, t; }" : "=r"(a) : "l"(p));
    return a;
}
__device__ __forceinline__ void cp16(uint32_t dst, const void* src){
    asm volatile("cp.async.cg.shared.global [%0], [%1], 16;" :: "r"(dst), "l"(src));
}
#define CP_COMMIT() asm volatile("cp.async.commit_group;" ::: "memory")
#define CP_WAIT0()  asm volatile("cp.async.wait_group 0;" ::: "memory")

__device__ __forceinline__ uint32_t packb(float hi, float lo){
    uint32_t r;
    asm("cvt.rn.bf16x2.f32 %0, %1, %2;" : "=r"(r) : "f"(hi), "f"(lo));
    return r;
}
__device__ __forceinline__ float unpk_lo(uint32_t u){ return __uint_as_float(u << 16); }
__device__ __forceinline__ float unpk_hi(uint32_t u){ return __uint_as_float(u & 0xFFFF0000u); }
__device__ __forceinline__ void split_pair(float x0, float x1, uint32_t &h, uint32_t &l){
    h = packb(x1, x0);
    l = packb(x1 - unpk_hi(h), x0 - unpk_lo(h));
}
__device__ __forceinline__ void mma_bf16(float c[4], uint32_t a0,uint32_t a1,uint32_t a2,uint32_t a3,
                                         uint32_t b0,uint32_t b1){
    asm volatile("mma.sync.aligned.m16n8k16.row.col.f32.bf16.bf16.f32 "
        "{%0,%1,%2,%3}, {%4,%5,%6,%7}, {%8,%9}, {%0,%1,%2,%3};"
        : "+f"(c[0]),"+f"(c[1]),"+f"(c[2]),"+f"(c[3])
        : "r"(a0),"r"(a1),"r"(a2),"r"(a3),"r"(b0),"r"(b1));
}

// ---- prep: fp32 K/V -> interleaved uint4 global buffers ----
__global__ __launch_bounds__(256)
void prep_split(const float* __restrict__ k, const float* __restrict__ v)
{
    int idx = blockIdx.x*256 + threadIdx.x;
    if (idx < BHc*Sc*16) {
        // K: one uint4 per (row, q): pairs c0=8s+t (d=16s+2t) and c0+4 (d=16s+2t+8)
        int row = idx >> 4, qq = idx & 15;
        const float* src = k + (size_t)row*Dc + 16*(qq>>2) + 2*(qq&3);
        float2 p0 = *(const float2*)src;
        float2 p1 = *(const float2*)(src + 8);
        uint32_t h0,l0,h1,l1;
        split_pair(p0.x, p0.y, h0, l0);
        split_pair(p1.x, p1.y, h1, l1);
        g_kq[idx] = make_uint4(h0, h1, l0, l1);
    } else {
        int vi = idx - BHc*Sc*16;
        if (vi < BHc*16*2048) {
            int n   = vi & 63;
            int g   = (vi >> 6) & 31;
            int T   = (vi >> 11) & 15;
            int bhv = vi >> 15;
            int s = g >> 2, tt = g & 3;
            int key0 = bhv*Sc + T*NT + 16*s + 2*tt;   // key 2*kp0
            const float* vs = v + (size_t)key0*Dc + n;
            float a0 = vs[0], a1 = vs[Dc], b0 = vs[8*Dc], b1 = vs[9*Dc];
            uint32_t ha,la,hb,lb;
            split_pair(a0, a1, ha, la);   // low half = even key
            split_pair(b0, b1, hb, lb);
            g_v[vi] = make_uint4(ha, hb, la, lb);
        }
    }
}

// ---- denom pre-pass: 1-term bf16-hi QK^T + exp + row-sum -> g_d ----
__global__ __launch_bounds__(256, 2)
void attn_denom(const float* __restrict__ q, const float* __restrict__ mask)
{
    extern __shared__ char smem[];
    float* MaskAll = (float*)(smem + 2*KREGB);
    const uint32_t sb = smem_u32(smem);

    const int tid  = threadIdx.x;
    const int w    = tid >> 5, lane = tid & 31;
    const int t    = lane & 3, qr = lane >> 2;
    const int bh   = blockIdx.x >> 4;
    const int mt   = blockIdx.x & 15;
    const int row0 = mt * MT;
    const int b    = bh / Hc;
    const int arow = 16*w + qr;

    // stage tile 0: 2048 uint4 chunks
    #pragma unroll
    for (int i = 0; i < 8; i++) {
        int f = tid + i*256;
        int r = f >> 4, qq = f & 15;
        cp16(sb + (r*KS4 + qq)*16, g_kq + (size_t)(bh*Sc + r)*16 + qq);
    }
    CP_COMMIT();

    {
        const float4* mg = (const float4*)(mask + b*Sc);
        #pragma unroll
        for (int i = 0; i < 2; i++) {
            int f = tid + i*256;
            float4 m = mg[f];
            m.x *= -1e9f; m.y *= -1e9f; m.z *= -1e9f; m.w *= -1e9f;
            ((float4*)MaskAll)[f] = m;
        }
    }

    // Q hi-fragments only (scaled by 1/8)
    uint32_t qhi[4][4];
    {
        const float* qp = q + (size_t)bh*Sc*Dc + (size_t)row0*Dc;
        #pragma unroll
        for (int s = 0; s < 4; s++) {
            float2 a = *(const float2*)&qp[(size_t)arow*Dc     + 16*s + 2*t];
            float2 bq= *(const float2*)&qp[(size_t)(arow+8)*Dc + 16*s + 2*t];
            float2 c = *(const float2*)&qp[(size_t)arow*Dc     + 16*s + 2*t + 8];
            float2 d = *(const float2*)&qp[(size_t)(arow+8)*Dc + 16*s + 2*t + 8];
            qhi[s][0] = packb(a.y*0.125f,  a.x*0.125f);
            qhi[s][1] = packb(bq.y*0.125f, bq.x*0.125f);
            qhi[s][2] = packb(c.y*0.125f,  c.x*0.125f);
            qhi[s][3] = packb(d.y*0.125f,  d.x*0.125f);
        }
    }

    float dsA = 0.f, dsB = 0.f;

    for (int tile = 0; tile < NKV; tile++) {
        const int cur = tile & 1;
        CP_WAIT0();
        __syncthreads();

        if (tile + 1 < NKV) {
            const uint32_t dst = sb + (cur ^ 1)*KREGB;
            #pragma unroll
            for (int i = 0; i < 8; i++) {
                int f = tid + i*256;
                int r = f >> 4, qq = f & 15;
                cp16(dst + (r*KS4 + qq)*16,
                     g_kq + (size_t)(bh*Sc + (tile+1)*NT + r)*16 + qq);
            }
            CP_COMMIT();
        }

        const uint4* Kq = (const uint4*)(smem + cur*KREGB);

        float S[16][4];
        #pragma unroll
        for (int j = 0; j < 16; j++) { S[j][0]=S[j][1]=S[j][2]=S[j][3]=0.f; }

        #pragma unroll
        for (int s = 0; s < 4; s++) {
            #pragma unroll
            for (int j = 0; j < 16; j++) {
                uint4 kk = Kq[(8*j + qr)*KS4 + 4*s + t];
                mma_bf16(S[j], qhi[s][0],qhi[s][1],qhi[s][2],qhi[s][3], kk.x, kk.y);
            }
        }

        const float* Ms = MaskAll + tile*NT;
        #pragma unroll
        for (int j = 0; j < 16; j++) {
            float2 m = *(float2*)&Ms[8*j + 2*t];
            dsA += __expf(S[j][0] + m.x) + __expf(S[j][1] + m.y);
            dsB += __expf(S[j][2] + m.x) + __expf(S[j][3] + m.y);
        }
    }

    dsA += __shfl_xor_sync(0xffffffffu, dsA, 1);
    dsA += __shfl_xor_sync(0xffffffffu, dsA, 2);
    dsB += __shfl_xor_sync(0xffffffffu, dsB, 1);
    dsB += __shfl_xor_sync(0xffffffffu, dsB, 2);
    if (t == 0) {
        g_d[bh*Sc + row0 + arow]     = dsA;
        g_d[bh*Sc + row0 + arow + 8] = dsB;
    }
}

__device__ __forceinline__ void stage_tile(uint32_t sb, int stage, int bh, int tile, int tid)
{
    const uint32_t dstK = sb + stage*PSTAGE;
    #pragma unroll
    for (int i = 0; i < 8; i++) {
        int f = tid + i*THREADS;            // 2048 K uint4 chunks
        int r = f >> 4, qq = f & 15;
        cp16(dstK + (r*KS4 + qq)*16,
             g_kq + (size_t)(bh*Sc + tile*NT + r)*16 + qq);
    }
    const uint32_t dstV = sb + stage*PSTAGE + KREGB;
    #pragma unroll
    for (int i = 0; i < 8; i++) {
        int f = tid + i*THREADS;            // 2048 V uint4 chunks
        int g = f >> 6, n = f & 63;
        cp16(dstV + (g*VS4 + n)*16,
             g_v + ((size_t)(bh*16 + tile)*2048 + g*64 + n));
    }
}

__global__ __launch_bounds__(THREADS, 1)
void attn_tc(const float* __restrict__ q, const float* __restrict__ mask,
             float* __restrict__ out, float* __restrict__ attn)
{
    extern __shared__ char smem[];
    float* MaskAll = (float*)(smem + OFF_MASKALL);
    const uint32_t sb = smem_u32(smem);

    const int tid  = threadIdx.x;
    const int w    = tid >> 5, lane = tid & 31;
    const int t    = lane & 3, qr = lane >> 2;
    const int bh   = blockIdx.x >> 4;
    const int mt   = blockIdx.x & 15;
    const int row0 = mt * MT;
    const int b    = bh / Hc;
    const size_t qkvBase = (size_t)bh * Sc * Dc;
    const int arow = 16*w + qr;           // warp-private q-row (and +8)

    // ---- prologue: stage tile 0 ----
    stage_tile(sb, 0, bh, 0, tid);
    CP_COMMIT();

    // ---- mask row -> smem (premultiplied by -1e9) ----
    {
        const float4* mg = (const float4*)(mask + b*Sc);
        #pragma unroll
        for (int i = 0; i < 2; i++) {
            int f = tid + i*THREADS;
            float4 m = mg[f];
            m.x *= -1e9f; m.y *= -1e9f; m.z *= -1e9f; m.w *= -1e9f;
            ((float4*)MaskAll)[f] = m;
        }
    }

    // ---- row log-denominators (from pre-pass) ----
    const float lndA = __logf(g_d[bh*Sc + row0 + arow]);
    const float lndB = __logf(g_d[bh*Sc + row0 + arow + 8]);

    // ---- Q A-fragments in registers (loaded once, scaled by 1/8, hi/lo split) ----
    uint32_t qhi[4][4], qlo[4][4];
    {
        const float* qp = q + qkvBase + (size_t)row0 * Dc;
        #pragma unroll
        for (int s = 0; s < 4; s++) {
            float2 a = *(const float2*)&qp[(size_t)arow*Dc     + 16*s + 2*t];
            float2 bq= *(const float2*)&qp[(size_t)(arow+8)*Dc + 16*s + 2*t];
            float2 c = *(const float2*)&qp[(size_t)arow*Dc     + 16*s + 2*t + 8];
            float2 d = *(const float2*)&qp[(size_t)(arow+8)*Dc + 16*s + 2*t + 8];
            split_pair(a.x*0.125f, a.y*0.125f, qhi[s][0], qlo[s][0]);
            split_pair(bq.x*0.125f, bq.y*0.125f, qhi[s][1], qlo[s][1]);
            split_pair(c.x*0.125f, c.y*0.125f, qhi[s][2], qlo[s][2]);
            split_pair(d.x*0.125f, d.y*0.125f, qhi[s][3], qlo[s][3]);
        }
    }

    float Co[8][4];
    #pragma unroll
    for (int n = 0; n < 8; n++) { Co[n][0]=Co[n][1]=Co[n][2]=Co[n][3]=0.f; }

    for (int tile = 0; tile < NKV; tile++) {
        const int cur = tile & 1;
        CP_WAIT0();
        __syncthreads();   // staged tile visible; prefetch buffer free (prev PV done)

        if (tile + 1 < NKV) {
            stage_tile(sb, cur ^ 1, bh, tile + 1, tid);
            CP_COMMIT();
        }

        const uint4* Kq = (const uint4*)(smem + cur*PSTAGE);
        const uint4* Vq = (const uint4*)(smem + cur*PSTAGE + KREGB);

        // ---- QK^T: 3-term bf16, one LDS.128 per fragment step ----
        float S[16][4];
        #pragma unroll
        for (int j = 0; j < 16; j++) { S[j][0]=S[j][1]=S[j][2]=S[j][3]=0.f; }

        #pragma unroll
        for (int s = 0; s < 4; s++) {
            #pragma unroll
            for (int j = 0; j < 16; j++) {
                uint4 kk = Kq[(8*j + qr)*KS4 + 4*s + t];
                mma_bf16(S[j], qhi[s][0],qhi[s][1],qhi[s][2],qhi[s][3], kk.x, kk.y);
                mma_bf16(S[j], qhi[s][0],qhi[s][1],qhi[s][2],qhi[s][3], kk.z, kk.w);
                mma_bf16(S[j], qlo[s][0],qlo[s][1],qlo[s][2],qlo[s][3], kk.x, kk.y);
            }
        }

        // ---- fused epilogue + PV: normalized e = exp(s + m - ln d) ----
        const float* Ms = MaskAll + tile*NT;
        float* abase  = attn + ((size_t)bh*Sc + row0 + arow)*Sc + (size_t)tile*NT;
        float* abase8 = abase + (size_t)8*Sc;
        #pragma unroll
        for (int s = 0; s < 8; s++) {
            float e[8];
            #pragma unroll
            for (int jj = 0; jj < 2; jj++) {
                const int j = 2*s + jj;
                float2 m = *(float2*)&Ms[8*j + 2*t];
                float e0 = __expf(S[j][0] + m.x - lndA);
                float e1 = __expf(S[j][1] + m.y - lndA);
                float e2 = __expf(S[j][2] + m.x - lndB);
                float e3 = __expf(S[j][3] + m.y - lndB);
                *(float2*)&abase[8*j + 2*t]  = make_float2(e0, e1);
                *(float2*)&abase8[8*j + 2*t] = make_float2(e2, e3);
                e[4*jj+0]=e0; e[4*jj+1]=e1; e[4*jj+2]=e2; e[4*jj+3]=e3;
            }
            uint32_t ah0,al0,ah1,al1,ah2,al2,ah3,al3;
            split_pair(e[0], e[1], ah0, al0);
            split_pair(e[2], e[3], ah1, al1);
            split_pair(e[4], e[5], ah2, al2);
            split_pair(e[6], e[7], ah3, al3);
            #pragma unroll
            for (int nb = 0; nb < 8; nb++) {
                uint4 vv = Vq[(4*s + t)*VS4 + 8*nb + qr];
                mma_bf16(Co[nb], ah0,ah1,ah2,ah3, vv.x, vv.y);
                mma_bf16(Co[nb], ah0,ah1,ah2,ah3, vv.z, vv.w);
                mma_bf16(Co[nb], al0,al1,al2,al3, vv.x, vv.y);
            }
        }
    }

    // ---- finalize: out already normalized (P was normalized) ----
    float* obase  = out + qkvBase + (size_t)(row0 + arow)*Dc;
    float* obase8 = obase + 8*Dc;
    #pragma unroll
    for (int n = 0; n < 8; n++) {
        *(float2*)&obase[8*n + 2*t]  = make_float2(Co[n][0], Co[n][1]);
        *(float2*)&obase8[8*n + 2*t] = make_float2(Co[n][2], Co[n][3]);
    }
}

extern "C" void kernel_launch(void* const* d_in, const int* in_sizes, int n_in,
                              void* d_out, int out_size)
{
    const float* q    = (const float*)d_in[0];
    const float* k    = (const float*)d_in[1];
    const float* v    = (const float*)d_in[2];
    const float* mask = (const float*)d_in[3];

    float* out  = (float*)d_out;
    float* attn = out + (size_t)Bc*Hc*Sc*Dc;

    const int prepTasks = BHc*Sc*16 + BHc*16*2048;    // 2,097,152
    prep_split<<<prepTasks/256, 256>>>(k, v);

    cudaFuncSetAttribute(attn_denom, cudaFuncAttributeMaxDynamicSharedMemorySize, DSMEM);
    attn_denom<<<BHc*16, 256, DSMEM>>>(q, mask);

    cudaFuncSetAttribute(attn_tc, cudaFuncAttributeMaxDynamicSharedMemorySize, SMEM_BYTES);
    attn_tc<<<BHc*16, THREADS, SMEM_BYTES>>>(q, mask, out, attn);
}

// round 17
// speedup vs baseline: 1.1528x; 1.1528x over previous
#include <cuda_runtime.h>
#include <cstdint>

#define Bc 2
#define Hc 16
#define Sc 2048
#define Dc 64
#define BHc (Bc*Hc)
#define MT 128
#define NT 128
#define NKV (Sc/NT)
#define TPC 8             // KV tiles per CTA (key-split in half)
#define THREADS 256

// packed strides (u32 units)
#define KSTR 36           // K row: 32 packed d-pairs + 4 pad  (36%32==4 -> conflict-free)
#define VSTR 72           // V row: 64 d entries + 8 pad       (72%32==8 -> conflict-free)

// attn_tc smem: two stages of [Khi|Klo|Vhi|Vlo], then mask
#define KBYTES (NT*KSTR*4)          // 18432
#define VBYTES ((NT/2)*VSTR*4)      // 18432
#define PSTAGE (2*KBYTES + 2*VBYTES)            // 73728 per stage
#define OFF_MASKALL (2*PSTAGE)                   // 147456
#define SMEM_BYTES (OFF_MASKALL + Sc*4)          // 155648

// attn_denom smem: two stages of Khi only, then mask
#define DSMEM (2*KBYTES + Sc*4)                  // 45056

#define OUT_ELEMS ((size_t)BHc*Sc*Dc)

__device__ float g_d[BHc*Sc];       // row denominators
__device__ float g_part[2*OUT_ELEMS];            // partial out (key-halves)
// pre-split packed bf16 buffers (32 MB total, static scratch)
__device__ uint32_t g_khi[(size_t)BHc*Sc*32];
__device__ uint32_t g_klo[(size_t)BHc*Sc*32];
__device__ uint32_t g_vhi[(size_t)BHc*(Sc/2)*64];
__device__ uint32_t g_vlo[(size_t)BHc*(Sc/2)*64];

__device__ __forceinline__ uint32_t smem_u32(const void* p){
    uint32_t a;
    asm("{ .reg .u64 t; cvta.to.shared.u64 t, %1; cvt.u32.u64 %0, t; }" : "=r"(a) : "l"(p));
    return a;
}
__device__ __forceinline__ void cp16(uint32_t dst, const void* src){
    asm volatile("cp.async.cg.shared.global [%0], [%1], 16;" :: "r"(dst), "l"(src));
}
#define CP_COMMIT() asm volatile("cp.async.commit_group;" ::: "memory")
#define CP_WAIT0()  asm volatile("cp.async.wait_group 0;" ::: "memory")

__device__ __forceinline__ uint32_t packb(float hi, float lo){
    uint32_t r;
    asm("cvt.rn.bf16x2.f32 %0, %1, %2;" : "=r"(r) : "f"(hi), "f"(lo));
    return r;
}
__device__ __forceinline__ float unpk_lo(uint32_t u){ return __uint_as_float(u << 16); }
__device__ __forceinline__ float unpk_hi(uint32_t u){ return __uint_as_float(u & 0xFFFF0000u); }
__device__ __forceinline__ void split_pair(float x0, float x1, uint32_t &h, uint32_t &l){
    h = packb(x1, x0);
    l = packb(x1 - unpk_hi(h), x0 - unpk_lo(h));
}
__device__ __forceinline__ void mma_bf16(float c[4], uint32_t a0,uint32_t a1,uint32_t a2,uint32_t a3,
                                         uint32_t b0,uint32_t b1){
    asm volatile("mma.sync.aligned.m16n8k16.row.col.f32.bf16.bf16.f32 "
        "{%0,%1,%2,%3}, {%4,%5,%6,%7}, {%8,%9}, {%0,%1,%2,%3};"
        : "+f"(c[0]),"+f"(c[1]),"+f"(c[2]),"+f"(c[3])
        : "r"(a0),"r"(a1),"r"(a2),"r"(a3),"r"(b0),"r"(b1));
}

// ---- prep: fp32 K/V -> packed bf16 hi/lo global buffers ----
__global__ __launch_bounds__(256)
void prep_split(const float* __restrict__ k, const float* __restrict__ v)
{
    int idx = blockIdx.x*256 + threadIdx.x;
    if (idx < BHc*Sc*16) {
        float4 x = ((const float4*)k)[(size_t)idx];
        uint32_t h0,l0,h1,l1;
        split_pair(x.x, x.y, h0, l0);
        split_pair(x.z, x.w, h1, l1);
        size_t o = ((size_t)(idx >> 4) << 5) + (size_t)((idx & 15) << 1);
        *(uint2*)&g_khi[o] = make_uint2(h0, h1);
        *(uint2*)&g_klo[o] = make_uint2(l0, l1);
    } else {
        int vi = idx - BHc*Sc*16;
        if (vi < BHc*(Sc/2)*16) {
            int kp_g = vi >> 4;
            int ch   = vi & 15;
            const float4* vp = (const float4*)v;
            float4 f0 = vp[(size_t)kp_g*32 + ch];
            float4 f1 = vp[(size_t)kp_g*32 + 16 + ch];
            uint32_t h0,l0,h1,l1,h2,l2,h3,l3;
            split_pair(f0.x, f1.x, h0, l0);
            split_pair(f0.y, f1.y, h1, l1);
            split_pair(f0.z, f1.z, h2, l2);
            split_pair(f0.w, f1.w, h3, l3);
            size_t o = (size_t)kp_g*64 + (size_t)ch*4;
            *(uint4*)&g_vhi[o] = make_uint4(h0,h1,h2,h3);
            *(uint4*)&g_vlo[o] = make_uint4(l0,l1,l2,l3);
        }
    }
}

// ---- denom pre-pass: 1-term bf16-hi QK^T + exp + row-sum -> g_d ----
__global__ __launch_bounds__(256, 2)
void attn_denom(const float* __restrict__ q, const float* __restrict__ mask)
{
    extern __shared__ char smem[];
    float* MaskAll = (float*)(smem + 2*KBYTES);
    const uint32_t sb = smem_u32(smem);

    const int tid  = threadIdx.x;
    const int w    = tid >> 5, lane = tid & 31;
    const int t    = lane & 3, qr = lane >> 2;
    const int bh   = blockIdx.x >> 4;
    const int mt   = blockIdx.x & 15;
    const int row0 = mt * MT;
    const int b    = bh / Hc;
    const int arow = 16*w + qr;

    #pragma unroll
    for (int i = 0; i < 4; i++) {
        int f = tid + i*256;
        int row = f >> 3, ch = f & 7;
        cp16(sb + row*(KSTR*4) + ch*16,
             g_khi + ((size_t)(bh*Sc + row))*32 + (size_t)ch*4);
    }
    CP_COMMIT();

    {
        const float4* mg = (const float4*)(mask + b*Sc);
        #pragma unroll
        for (int i = 0; i < 2; i++) {
            int f = tid + i*256;
            float4 m = mg[f];
            m.x *= -1e9f; m.y *= -1e9f; m.z *= -1e9f; m.w *= -1e9f;
            ((float4*)MaskAll)[f] = m;
        }
    }

    uint32_t qhi[4][4];
    {
        const float* qp = q + (size_t)bh*Sc*Dc + (size_t)row0*Dc;
        #pragma unroll
        for (int s = 0; s < 4; s++) {
            float2 a = *(const float2*)&qp[(size_t)arow*Dc     + 16*s + 2*t];
            float2 bq= *(const float2*)&qp[(size_t)(arow+8)*Dc + 16*s + 2*t];
            float2 c = *(const float2*)&qp[(size_t)arow*Dc     + 16*s + 2*t + 8];
            float2 d = *(const float2*)&qp[(size_t)(arow+8)*Dc + 16*s + 2*t + 8];
            qhi[s][0] = packb(a.y*0.125f,  a.x*0.125f);
            qhi[s][1] = packb(bq.y*0.125f, bq.x*0.125f);
            qhi[s][2] = packb(c.y*0.125f,  c.x*0.125f);
            qhi[s][3] = packb(d.y*0.125f,  d.x*0.125f);
        }
    }

    float dsA = 0.f, dsB = 0.f;

    for (int tile = 0; tile < NKV; tile++) {
        const int cur = tile & 1;
        CP_WAIT0();
        __syncthreads();

        if (tile + 1 < NKV) {
            const uint32_t dst = sb + (cur ^ 1)*KBYTES;
            #pragma unroll
            for (int i = 0; i < 4; i++) {
                int f = tid + i*256;
                int row = f >> 3, ch = f & 7;
                cp16(dst + row*(KSTR*4) + ch*16,
                     g_khi + ((size_t)(bh*Sc + (tile+1)*NT + row))*32 + (size_t)ch*4);
            }
            CP_COMMIT();
        }

        const uint32_t* Khi = (const uint32_t*)(smem + cur*KBYTES);

        float S[16][4];
        #pragma unroll
        for (int j = 0; j < 16; j++) { S[j][0]=S[j][1]=S[j][2]=S[j][3]=0.f; }

        #pragma unroll
        for (int s = 0; s < 4; s++) {
            #pragma unroll
            for (int j = 0; j < 16; j++) {
                const uint32_t* kh = &Khi[(8*j + qr)*KSTR + 8*s + t];
                mma_bf16(S[j], qhi[s][0],qhi[s][1],qhi[s][2],qhi[s][3], kh[0], kh[4]);
            }
        }

        const float* Ms = MaskAll + tile*NT;
        #pragma unroll
        for (int j = 0; j < 16; j++) {
            float2 m = *(float2*)&Ms[8*j + 2*t];
            dsA += __expf(S[j][0] + m.x) + __expf(S[j][1] + m.y);
            dsB += __expf(S[j][2] + m.x) + __expf(S[j][3] + m.y);
        }
    }

    dsA += __shfl_xor_sync(0xffffffffu, dsA, 1);
    dsA += __shfl_xor_sync(0xffffffffu, dsA, 2);
    dsB += __shfl_xor_sync(0xffffffffu, dsB, 1);
    dsB += __shfl_xor_sync(0xffffffffu, dsB, 2);
    if (t == 0) {
        g_d[bh*Sc + row0 + arow]     = dsA;
        g_d[bh*Sc + row0 + arow + 8] = dsB;
    }
}

__device__ __forceinline__ void stage_tile(uint32_t sb, int stage, int bh, int tile, int tid)
{
    const uint32_t dstK = sb + stage*PSTAGE;
    #pragma unroll
    for (int i = 0; i < 8; i++) {
        int f = tid + i*THREADS;
        int hl = f >> 10, r = f & 1023;
        int row = r >> 3, ch = r & 7;
        const uint32_t* src = (hl ? g_klo : g_khi)
            + ((size_t)(bh*Sc + tile*NT + row))*32 + (size_t)ch*4;
        cp16(dstK + hl*KBYTES + row*(KSTR*4) + ch*16, src);
    }
    const uint32_t dstV = sb + stage*PSTAGE + 2*KBYTES;
    #pragma unroll
    for (int i = 0; i < 8; i++) {
        int f = tid + i*THREADS;
        int hl = f >> 10, r = f & 1023;
        int kp = r >> 4, ch = r & 15;
        const uint32_t* src = (hl ? g_vlo : g_vhi)
            + ((size_t)(bh*(Sc/2) + tile*(NT/2) + kp))*64 + (size_t)ch*4;
        cp16(dstV + hl*VBYTES + kp*(VSTR*4) + ch*16, src);
    }
}

__global__ __launch_bounds__(THREADS, 1)
void attn_tc(const float* __restrict__ q, const float* __restrict__ mask,
             float* __restrict__ attn)
{
    extern __shared__ char smem[];
    float* MaskAll = (float*)(smem + OFF_MASKALL);
    const uint32_t sb = smem_u32(smem);

    const int tid  = threadIdx.x;
    const int w    = tid >> 5, lane = tid & 31;
    const int t    = lane & 3, qr = lane >> 2;
    const int blk  = blockIdx.x;
    const int kh   = blk & 1;             // key-half
    const int mt   = (blk >> 1) & 15;
    const int bh   = blk >> 5;
    const int row0 = mt * MT;
    const int t0   = kh * TPC;
    const int b    = bh / Hc;
    const size_t qkvBase = (size_t)bh * Sc * Dc;
    const int arow = 16*w + qr;           // warp-private q-row (and +8)

    // ---- prologue: stage first tile of this half ----
    stage_tile(sb, 0, bh, t0, tid);
    CP_COMMIT();

    // ---- mask row -> smem (premultiplied by -1e9) ----
    {
        const float4* mg = (const float4*)(mask + b*Sc);
        #pragma unroll
        for (int i = 0; i < 2; i++) {
            int f = tid + i*THREADS;
            float4 m = mg[f];
            m.x *= -1e9f; m.y *= -1e9f; m.z *= -1e9f; m.w *= -1e9f;
            ((float4*)MaskAll)[f] = m;
        }
    }

    // ---- row log-denominators (from pre-pass) ----
    const float lndA = __logf(g_d[bh*Sc + row0 + arow]);
    const float lndB = __logf(g_d[bh*Sc + row0 + arow + 8]);

    // ---- Q A-fragments in registers (loaded once, scaled by 1/8, hi/lo split) ----
    uint32_t qhi[4][4], qlo[4][4];
    {
        const float* qp = q + qkvBase + (size_t)row0 * Dc;
        #pragma unroll
        for (int s = 0; s < 4; s++) {
            float2 a = *(const float2*)&qp[(size_t)arow*Dc     + 16*s + 2*t];
            float2 bq= *(const float2*)&qp[(size_t)(arow+8)*Dc + 16*s + 2*t];
            float2 c = *(const float2*)&qp[(size_t)arow*Dc     + 16*s + 2*t + 8];
            float2 d = *(const float2*)&qp[(size_t)(arow+8)*Dc + 16*s + 2*t + 8];
            split_pair(a.x*0.125f, a.y*0.125f, qhi[s][0], qlo[s][0]);
            split_pair(bq.x*0.125f, bq.y*0.125f, qhi[s][1], qlo[s][1]);
            split_pair(c.x*0.125f, c.y*0.125f, qhi[s][2], qlo[s][2]);
            split_pair(d.x*0.125f, d.y*0.125f, qhi[s][3], qlo[s][3]);
        }
    }

    float Co[8][4];
    #pragma unroll
    for (int n = 0; n < 8; n++) { Co[n][0]=Co[n][1]=Co[n][2]=Co[n][3]=0.f; }

    for (int it = 0; it < TPC; it++) {
        const int tile = t0 + it;
        const int cur = it & 1;
        CP_WAIT0();
        __syncthreads();   // staged tile visible; prefetch buffer free (prev PV done)

        if (it + 1 < TPC) {
            stage_tile(sb, cur ^ 1, bh, tile + 1, tid);
            CP_COMMIT();
        }

        const uint32_t* Khi = (const uint32_t*)(smem + cur*PSTAGE);
        const uint32_t* Klo = Khi + KBYTES/4;
        const uint32_t* Vhi = Khi + 2*(KBYTES/4);
        const uint32_t* Vlo = Khi + 2*(KBYTES/4) + VBYTES/4;

        // ---- QK^T: 3-term bf16 (qhi*khi + qhi*klo + qlo*khi) ----
        float S[16][4];
        #pragma unroll
        for (int j = 0; j < 16; j++) { S[j][0]=S[j][1]=S[j][2]=S[j][3]=0.f; }

        #pragma unroll
        for (int s = 0; s < 4; s++) {
            #pragma unroll
            for (int j = 0; j < 16; j++) {
                const uint32_t* kh2 = &Khi[(8*j + qr)*KSTR + 8*s + t];
                const uint32_t* kl2 = &Klo[(8*j + qr)*KSTR + 8*s + t];
                uint32_t bh0 = kh2[0], bh1 = kh2[4];
                uint32_t bl0 = kl2[0], bl1 = kl2[4];
                mma_bf16(S[j], qhi[s][0],qhi[s][1],qhi[s][2],qhi[s][3], bh0,bh1);
                mma_bf16(S[j], qhi[s][0],qhi[s][1],qhi[s][2],qhi[s][3], bl0,bl1);
                mma_bf16(S[j], qlo[s][0],qlo[s][1],qlo[s][2],qlo[s][3], bh0,bh1);
            }
        }

        // ---- fused epilogue + PV: normalized e = exp(s + m - ln d) ----
        const float* Ms = MaskAll + tile*NT;
        float* abase  = attn + ((size_t)bh*Sc + row0 + arow)*Sc + (size_t)tile*NT;
        float* abase8 = abase + (size_t)8*Sc;
        #pragma unroll
        for (int s = 0; s < 8; s++) {
            float e[8];
            #pragma unroll
            for (int jj = 0; jj < 2; jj++) {
                const int j = 2*s + jj;
                float2 m = *(float2*)&Ms[8*j + 2*t];
                float e0 = __expf(S[j][0] + m.x - lndA);
                float e1 = __expf(S[j][1] + m.y - lndA);
                float e2 = __expf(S[j][2] + m.x - lndB);
                float e3 = __expf(S[j][3] + m.y - lndB);
                *(float2*)&abase[8*j + 2*t]  = make_float2(e0, e1);
                *(float2*)&abase8[8*j + 2*t] = make_float2(e2, e3);
                e[4*jj+0]=e0; e[4*jj+1]=e1; e[4*jj+2]=e2; e[4*jj+3]=e3;
            }
            uint32_t ah0,al0,ah1,al1,ah2,al2,ah3,al3;
            split_pair(e[0], e[1], ah0, al0);
            split_pair(e[2], e[3], ah1, al1);
            split_pair(e[4], e[5], ah2, al2);
            split_pair(e[6], e[7], ah3, al3);
            const int vrow = 8*s + t;
            #pragma unroll
            for (int nb = 0; nb < 8; nb++) {
                const uint32_t* vh = &Vhi[vrow*VSTR + 8*nb + qr];
                const uint32_t* vl = &Vlo[vrow*VSTR + 8*nb + qr];
                uint32_t b0h = vh[0], b1h = vh[4*VSTR];
                uint32_t b0l = vl[0], b1l = vl[4*VSTR];
                mma_bf16(Co[nb], ah0,ah1,ah2,ah3, b0h,b1h);
                mma_bf16(Co[nb], ah0,ah1,ah2,ah3, b0l,b1l);
                mma_bf16(Co[nb], al0,al1,al2,al3, b0h,b1h);
            }
        }
    }

    // ---- finalize: write partial out for this key-half ----
    float* pbase  = g_part + (size_t)kh*OUT_ELEMS + qkvBase + (size_t)(row0 + arow)*Dc;
    float* pbase8 = pbase + 8*Dc;
    #pragma unroll
    for (int n = 0; n < 8; n++) {
        *(float2*)&pbase[8*n + 2*t]  = make_float2(Co[n][0], Co[n][1]);
        *(float2*)&pbase8[8*n + 2*t] = make_float2(Co[n][2], Co[n][3]);
    }
}

__global__ __launch_bounds__(256)
void reduce_out(float* __restrict__ out)
{
    size_t i = (size_t)blockIdx.x*256 + threadIdx.x;     // float4 index
    const float4* p0 = (const float4*)g_part;
    const float4* p1 = (const float4*)(g_part + OUT_ELEMS);
    float4 a = p0[i], b = p1[i];
    a.x += b.x; a.y += b.y; a.z += b.z; a.w += b.w;
    ((float4*)out)[i] = a;
}

extern "C" void kernel_launch(void* const* d_in, const int* in_sizes, int n_in,
                              void* d_out, int out_size)
{
    const float* q    = (const float*)d_in[0];
    const float* k    = (const float*)d_in[1];
    const float* v    = (const float*)d_in[2];
    const float* mask = (const float*)d_in[3];

    float* out  = (float*)d_out;
    float* attn = out + OUT_ELEMS;

    const int prepTasks = BHc*Sc*16 + BHc*(Sc/2)*16;
    prep_split<<<(prepTasks + 255)/256, 256>>>(k, v);

    cudaFuncSetAttribute(attn_denom, cudaFuncAttributeMaxDynamicSharedMemorySize, DSMEM);
    attn_denom<<<BHc*16, 256, DSMEM>>>(q, mask);

    cudaFuncSetAttribute(attn_tc, cudaFuncAttributeMaxDynamicSharedMemorySize, SMEM_BYTES);
    attn_tc<<<BHc*32, THREADS, SMEM_BYTES>>>(q, mask, attn);

    reduce_out<<<(int)(OUT_ELEMS/4/256), 256>>>(out);
}